// round 6
// baseline (speedup 1.0000x reference)
#include <cuda_runtime.h>
#include <cstdint>

// Fixed problem shapes: E<=4096, IN=OUT=256, N_NODES=1024
#define MAX_E 4096
#define NN    1024
#define FC    256
#define FC4   64
#define NB    132          // grid size: <= 148 SMs -> wave-1 co-resident
#define NT    256
#define GT    (NB * NT)

// ---------------- device scratch ----------------
__device__ unsigned long long g_bar;     // monotonic barrier ticket (never reset)
__device__ int   g_flagA, g_flagNZ;
__device__ int   g_hs[NN], g_hd[NN], g_sl[NN];
__device__ int   g_off_src[NN + 1], g_off_dst[NN + 1];
__device__ int   g_cur_src[NN], g_cur_dst[NN];
__device__ int   g_lst_src[MAX_E], g_lst_dst[MAX_E];
__device__ float g_w[MAX_E];
__device__ float g_t[NN * FC];
__device__ float g_T[NN * FC];

// grid-wide barrier: monotonic epochs, graph-replay safe
__device__ __forceinline__ void grid_bar() {
    __syncthreads();
    __threadfence();
    if (threadIdx.x == 0) {
        unsigned long long ticket = atomicAdd(&g_bar, 1ULL);
        unsigned long long target = (ticket / gridDim.x + 1ULL) * gridDim.x;
        while (atomicAdd(&g_bar, 0ULL) < target) { }
    }
    __syncthreads();
    __threadfence();
}

__global__ __launch_bounds__(NT)
void k_all(const float* __restrict__ x, const float* __restrict__ W,
           const int* __restrict__ ei, const void* __restrict__ isdir,
           float* __restrict__ y, int E) {
    const int tid  = threadIdx.x;
    const int b    = blockIdx.x;
    const int gtid = b * NT + tid;

    __shared__ float As[16][33];
    __shared__ float Bs[16][65];
    __shared__ int   s_wsum[16];      // scan warp partials (8 src + 8 dst)

    // ---------------- P0: zero scratch ----------------
    for (int i = gtid; i < NN; i += GT) {
        g_hs[i] = 0; g_hd[i] = 0; g_sl[i] = 0;
        g_cur_src[i] = 0; g_cur_dst[i] = 0;
    }
    if (gtid == 0) { g_flagA = 0; g_flagNZ = 0; }
    grid_bar();

    // ---------------- P1: histograms + bool-layout flags ----------------
    const unsigned char* bb = (const unsigned char*)isdir;
    for (int e = gtid; e < E; e += GT) {
        unsigned char v = bb[e];
        if (v) {
            atomicOr(&g_flagNZ, 1);
            if (e & 3) atomicOr(&g_flagA, 1);
        }
        int s = ei[e], d = ei[E + e];
        atomicAdd(&g_hs[s], 1);
        atomicAdd(&g_hd[d], 1);
        if (s == d) atomicAdd(&g_sl[s], 1);
    }
    grid_bar();

    // ---------------- P2: exclusive scan of hs/hd (block 0) ----------------
    if (b == 0) {
        int lane = tid & 31, wid = tid >> 5;
        // each thread owns 4 consecutive bins
        int i0 = tid * 4;
        int a0 = g_hs[i0], a1 = g_hs[i0 + 1], a2 = g_hs[i0 + 2], a3 = g_hs[i0 + 3];
        int c0 = g_hd[i0], c1 = g_hd[i0 + 1], c2 = g_hd[i0 + 2], c3 = g_hd[i0 + 3];
        int i1 = a0 + a1, i2 = i1 + a2, i3 = i2 + a3;        // inclusive within thread
        int j1 = c0 + c1, j2 = j1 + c2, j3 = j2 + c3;
        int ts = i3, td = j3;
        #pragma unroll
        for (int o = 1; o < 32; o <<= 1) {
            int u = __shfl_up_sync(0xffffffffu, ts, o); if (lane >= o) ts += u;
            int v = __shfl_up_sync(0xffffffffu, td, o); if (lane >= o) td += v;
        }
        if (lane == 31) { s_wsum[wid] = ts; s_wsum[8 + wid] = td; }
        __syncthreads();
        if (wid == 0 && lane < 16) {
            int v = s_wsum[lane];
            #pragma unroll
            for (int o = 1; o < 8; o <<= 1) {
                int u = __shfl_up_sync(0xffffu, v, o);
                if ((lane & 7) >= o) v += u;
            }
            s_wsum[lane] = v;
        }
        __syncthreads();
        int bs = (wid ? s_wsum[wid - 1] : 0) + (ts - i3);     // exclusive base (src)
        int bd = (wid ? s_wsum[8 + wid - 1] : 0) + (td - j3); // exclusive base (dst)
        g_off_src[i0]     = bs;        g_off_dst[i0]     = bd;
        g_off_src[i0 + 1] = bs + a0;   g_off_dst[i0 + 1] = bd + c0;
        g_off_src[i0 + 2] = bs + i1;   g_off_dst[i0 + 2] = bd + j1;
        g_off_src[i0 + 3] = bs + i2;   g_off_dst[i0 + 3] = bd + j2;
        if (tid == NT - 1) { g_off_src[NN] = bs + i3; g_off_dst[NN] = bd + j3; }
    }
    grid_bar();

    // ---------------- P3: weights + CSR fill ----------------
    {
        int flagA = g_flagA, flagNZ = g_flagNZ;
        for (int e = gtid; e < E; e += GT) {
            int s = ei[e], d = ei[E + e];
            float w = 0.0f;
            if (s != d) {
                int deg = g_hs[s] + g_hd[s] + g_hs[d] + g_hd[d]
                        - 2 * (g_sl[s] + g_sl[d]);
                int dir;
                if (flagA)       dir = bb[e] != 0;
                else if (flagNZ) dir = ((const int*)isdir)[e] != 0;
                else             dir = 0;
                w = (dir ? -1.0f : 1.0f) * rsqrtf((float)deg);
            }
            g_w[e] = w;
            int p = g_off_src[s] + atomicAdd(&g_cur_src[s], 1);
            g_lst_src[p] = e;
            int q = g_off_dst[d] + atomicAdd(&g_cur_dst[d], 1);
            g_lst_dst[q] = e;
        }
    }
    grid_bar();

    // ---------------- P4: t[n] = sum_dst w x - sum_src w x ----------------
    {
        int sub = tid >> 6;          // 4 nodes per block-iteration
        int c4  = tid & 63;
        for (int g = b; g < NN / 4; g += NB) {
            int n = g * 4 + sub;
            float4 acc = make_float4(0.f, 0.f, 0.f, 0.f);
            #pragma unroll
            for (int side = 0; side < 2; side++) {
                const int* lst; int lo, hi; float sgn;
                if (side == 0) { lo = g_off_src[n]; hi = g_off_src[n + 1]; lst = g_lst_src; sgn = -1.f; }
                else           { lo = g_off_dst[n]; hi = g_off_dst[n + 1]; lst = g_lst_dst; sgn =  1.f; }
                for (int j = lo; j < hi; j++) {
                    int e = lst[j];                       // broadcast within 64-group
                    float w = sgn * g_w[e];
                    float4 v = ((const float4*)x)[e * FC4 + c4];
                    acc.x = fmaf(w, v.x, acc.x);
                    acc.y = fmaf(w, v.y, acc.y);
                    acc.z = fmaf(w, v.z, acc.z);
                    acc.w = fmaf(w, v.w, acc.w);
                }
            }
            ((float4*)g_t)[n * FC4 + c4] = acc;
        }
    }
    grid_bar();

    // ---------------- P5: GEMM T = t @ W^T  (blocks 0..127) ----------------
    if (b < 128) {
        int gx = b & 3, gy = b >> 2;
        int m0 = gy * 32, n0 = gx * 64;
        int tx = tid & 15, ty = tid >> 4;      // 16 col-groups x 16 row-groups
        float acc[2][4];
        #pragma unroll
        for (int i = 0; i < 2; i++)
            #pragma unroll
            for (int j = 0; j < 4; j++) acc[i][j] = 0.0f;

        for (int k0 = 0; k0 < FC; k0 += 16) {
            if (tid < 128) {                   // A tile 32x16
                int row = tid >> 2, kq = (tid & 3) << 2;
                float4 v = *(const float4*)&g_t[(m0 + row) * FC + k0 + kq];
                As[kq + 0][row] = v.x; As[kq + 1][row] = v.y;
                As[kq + 2][row] = v.z; As[kq + 3][row] = v.w;
            }
            {                                  // B tile 64x16
                int n = tid >> 2, kq = (tid & 3) << 2;
                float4 v = *(const float4*)&W[(n0 + n) * FC + k0 + kq];
                Bs[kq + 0][n] = v.x; Bs[kq + 1][n] = v.y;
                Bs[kq + 2][n] = v.z; Bs[kq + 3][n] = v.w;
            }
            __syncthreads();
            #pragma unroll
            for (int k = 0; k < 16; k++) {
                float a[2], w4[4];
                a[0] = As[k][ty * 2 + 0];
                a[1] = As[k][ty * 2 + 1];
                #pragma unroll
                for (int j = 0; j < 4; j++) w4[j] = Bs[k][tx * 4 + j];
                #pragma unroll
                for (int i = 0; i < 2; i++)
                    #pragma unroll
                    for (int j = 0; j < 4; j++)
                        acc[i][j] = fmaf(a[i], w4[j], acc[i][j]);
            }
            __syncthreads();
        }
        #pragma unroll
        for (int i = 0; i < 2; i++) {
            float4 v = make_float4(acc[i][0], acc[i][1], acc[i][2], acc[i][3]);
            *(float4*)&g_T[(m0 + ty * 2 + i) * FC + n0 + tx * 4] = v;
        }
    }
    grid_bar();

    // ---------------- P6: y_e = w_e * (T[dst] - T[src]) ----------------
    for (int i = gtid; i < E * FC4; i += GT) {
        int e = i >> 6, c4 = i & 63;
        float w = g_w[e];
        int s = ei[e], d = ei[E + e];
        float4 vd = ((const float4*)g_T)[d * FC4 + c4];
        float4 vs = ((const float4*)g_T)[s * FC4 + c4];
        float4 o;
        o.x = w * (vd.x - vs.x); o.y = w * (vd.y - vs.y);
        o.z = w * (vd.z - vs.z); o.w = w * (vd.w - vs.w);
        ((float4*)y)[i] = o;
    }
}

// ---------------- launch ---------------------------------------------------
extern "C" void kernel_launch(void* const* d_in, const int* in_sizes, int n_in,
                              void* d_out, int out_size) {
    const float* x     = (const float*)d_in[0];   // [E, 256]
    const float* W     = (const float*)d_in[1];   // [256, 256]
    const int*   ei    = (const int*)d_in[2];     // [2, E]
    const void*  isdir = d_in[3];                 // [E] bool or int32

    int E = in_sizes[2] / 2;
    float* y = (float*)d_out;

    k_all<<<NB, NT>>>(x, W, ei, isdir, y, E);
}

// round 7
// speedup vs baseline: 1.0836x; 1.0836x over previous
#include <cuda_runtime.h>
#include <cstdint>

// Fixed problem shapes: E<=4096, IN=OUT=256, N_NODES=1024
#define MAX_E 4096
#define NN    1024
#define FC    256
#define FC4   64
#define NB    132          // <= SM count -> wave-1 co-resident
#define NT    256
#define GT    (NB * NT)

// ---------------- device scratch (loader-zeroed; self-cleaned per run) -----
__device__ unsigned long long g_bar;     // monotonic barrier ticket (never reset)
__device__ int   g_flagA, g_flagNZ;      // sticky layout flags (deterministic)
__device__ int   g_hs[NN], g_hd[NN], g_sl[NN];      // zeroed at end of run
__device__ int   g_cur_src[NN], g_cur_dst[NN];      // zeroed at end of run
__device__ int   g_lst_src[MAX_E], g_lst_dst[MAX_E];
__device__ float g_w[MAX_E];
__device__ float g_t[NN * FC];
__device__ float g_T[NN * FC];

// grid barrier: monotonic epochs (replay-safe), RED arrive + LOAD spin
__device__ __forceinline__ void grid_bar() {
    __syncthreads();
    if (threadIdx.x == 0) {
        __threadfence();                                   // publish prior writes
        unsigned long long ticket = atomicAdd(&g_bar, 1ULL);
        unsigned long long target = (ticket / gridDim.x + 1ULL) * gridDim.x;
        volatile unsigned long long* p = &g_bar;
        while (*p < target) { }                            // plain L2 load spin
    }
    __syncthreads();
}

__global__ __launch_bounds__(NT)
void k_all(const float* __restrict__ x, const float* __restrict__ W,
           const int* __restrict__ ei, const void* __restrict__ isdir,
           float* __restrict__ y, int E) {
    const int tid  = threadIdx.x;
    const int b    = blockIdx.x;
    const int gtid = b * NT + tid;

    __shared__ int   offs[NN + 1], offd[NN + 1];   // per-block CSR offsets
    __shared__ float As[16][33];
    __shared__ float Bs[16][65];
    __shared__ int   swsum[16];

    // ================= P1: histograms + layout flags =================
    const unsigned char* bb = (const unsigned char*)isdir;
    for (int e = gtid; e < E; e += GT) {
        unsigned char v = bb[e];
        if (v) {
            atomicOr(&g_flagNZ, 1);
            if (e & 3) atomicOr(&g_flagA, 1);
        }
        int s = ei[e], d = ei[E + e];
        atomicAdd(&g_hs[s], 1);
        atomicAdd(&g_hd[d], 1);
        if (s == d) atomicAdd(&g_sl[s], 1);
    }
    grid_bar();

    // ============ P2: per-block smem scan + CSR fill + weights ============
    {
        int lane = tid & 31, wid = tid >> 5;
        int i0 = tid * 4;
        int a0 = g_hs[i0], a1 = g_hs[i0 + 1], a2 = g_hs[i0 + 2], a3 = g_hs[i0 + 3];
        int c0 = g_hd[i0], c1 = g_hd[i0 + 1], c2 = g_hd[i0 + 2], c3 = g_hd[i0 + 3];
        int i1 = a0 + a1, i2 = i1 + a2, i3 = i2 + a3;
        int j1 = c0 + c1, j2 = j1 + c2, j3 = j2 + c3;
        int ts = i3, td = j3;
        #pragma unroll
        for (int o = 1; o < 32; o <<= 1) {
            int u = __shfl_up_sync(0xffffffffu, ts, o); if (lane >= o) ts += u;
            int v = __shfl_up_sync(0xffffffffu, td, o); if (lane >= o) td += v;
        }
        if (lane == 31) { swsum[wid] = ts; swsum[8 + wid] = td; }
        __syncthreads();
        if (wid == 0 && lane < 16) {
            int v = swsum[lane];
            #pragma unroll
            for (int o = 1; o < 8; o <<= 1) {
                int u = __shfl_up_sync(0xffffu, v, o);
                if ((lane & 7) >= o) v += u;
            }
            swsum[lane] = v;
        }
        __syncthreads();
        int bs = (wid ? swsum[wid - 1] : 0) + (ts - i3);
        int bd = (wid ? swsum[8 + wid - 1] : 0) + (td - j3);
        offs[i0]     = bs;       offd[i0]     = bd;
        offs[i0 + 1] = bs + a0;  offd[i0 + 1] = bd + c0;
        offs[i0 + 2] = bs + i1;  offd[i0 + 2] = bd + j1;
        offs[i0 + 3] = bs + i2;  offd[i0 + 3] = bd + j2;
        if (tid == NT - 1) { offs[NN] = bs + i3; offd[NN] = bd + j3; }
        __syncthreads();

        int flagA = g_flagA, flagNZ = g_flagNZ;
        for (int e = gtid; e < E; e += GT) {
            int s = ei[e], d = ei[E + e];
            float w = 0.0f;
            if (s != d) {
                int deg = (offs[s + 1] - offs[s]) + (offd[s + 1] - offd[s])
                        + (offs[d + 1] - offs[d]) + (offd[d + 1] - offd[d])
                        - 2 * (g_sl[s] + g_sl[d]);
                int dir;
                if (flagA)       dir = bb[e] != 0;
                else if (flagNZ) dir = ((const int*)isdir)[e] != 0;
                else             dir = 0;
                w = (dir ? -1.0f : 1.0f) * rsqrtf((float)deg);
            }
            g_w[e] = w;
            int p = offs[s] + atomicAdd(&g_cur_src[s], 1);
            g_lst_src[p] = e;
            int q = offd[d] + atomicAdd(&g_cur_dst[d], 1);
            g_lst_dst[q] = e;
        }
    }
    grid_bar();

    // ============ P3: t[n] = sum_dst w x - sum_src w x  (smem offsets) =====
    {
        int sub = tid >> 6;          // 4 nodes per block-iteration
        int c4  = tid & 63;
        for (int g = b; g < NN / 4; g += NB) {
            int n = g * 4 + sub;
            float4 acc = make_float4(0.f, 0.f, 0.f, 0.f);
            #pragma unroll
            for (int side = 0; side < 2; side++) {
                const int* lst; int lo, hi; float sgn;
                if (side == 0) { lo = offs[n]; hi = offs[n + 1]; lst = g_lst_src; sgn = -1.f; }
                else           { lo = offd[n]; hi = offd[n + 1]; lst = g_lst_dst; sgn =  1.f; }
                for (int j = lo; j < hi; j += 4) {         // 4-way MLP
                    int m = hi - j;
                    int e0 = lst[j];
                    int e1 = (m > 1) ? lst[j + 1] : e0;
                    int e2 = (m > 2) ? lst[j + 2] : e0;
                    int e3 = (m > 3) ? lst[j + 3] : e0;
                    float w0 = sgn * g_w[e0];
                    float w1 = (m > 1) ? sgn * g_w[e1] : 0.f;
                    float w2 = (m > 2) ? sgn * g_w[e2] : 0.f;
                    float w3 = (m > 3) ? sgn * g_w[e3] : 0.f;
                    float4 v0 = ((const float4*)x)[e0 * FC4 + c4];
                    float4 v1 = ((const float4*)x)[e1 * FC4 + c4];
                    float4 v2 = ((const float4*)x)[e2 * FC4 + c4];
                    float4 v3 = ((const float4*)x)[e3 * FC4 + c4];
                    acc.x += w0 * v0.x + w1 * v1.x + w2 * v2.x + w3 * v3.x;
                    acc.y += w0 * v0.y + w1 * v1.y + w2 * v2.y + w3 * v3.y;
                    acc.z += w0 * v0.z + w1 * v1.z + w2 * v2.z + w3 * v3.z;
                    acc.w += w0 * v0.w + w1 * v1.w + w2 * v2.w + w3 * v3.w;
                }
            }
            ((float4*)g_t)[n * FC4 + c4] = acc;
        }
    }
    grid_bar();

    // ============ P4: GEMM T = t @ W^T  (blocks 0..127) ============
    if (b < 128) {
        int gx = b & 3, gy = b >> 2;
        int m0 = gy * 32, n0 = gx * 64;
        int tx = tid & 15, ty = tid >> 4;
        float acc[2][4];
        #pragma unroll
        for (int i = 0; i < 2; i++)
            #pragma unroll
            for (int j = 0; j < 4; j++) acc[i][j] = 0.0f;

        for (int k0 = 0; k0 < FC; k0 += 16) {
            if (tid < 128) {                   // A tile 32x16
                int row = tid >> 2, kq = (tid & 3) << 2;
                float4 v = *(const float4*)&g_t[(m0 + row) * FC + k0 + kq];
                As[kq + 0][row] = v.x; As[kq + 1][row] = v.y;
                As[kq + 2][row] = v.z; As[kq + 3][row] = v.w;
            }
            {                                  // B tile 64x16
                int n = tid >> 2, kq = (tid & 3) << 2;
                float4 v = *(const float4*)&W[(n0 + n) * FC + k0 + kq];
                Bs[kq + 0][n] = v.x; Bs[kq + 1][n] = v.y;
                Bs[kq + 2][n] = v.z; Bs[kq + 3][n] = v.w;
            }
            __syncthreads();
            #pragma unroll
            for (int k = 0; k < 16; k++) {
                float a0 = As[k][ty * 2 + 0];
                float a1 = As[k][ty * 2 + 1];
                float w4[4];
                #pragma unroll
                for (int j = 0; j < 4; j++) w4[j] = Bs[k][tx * 4 + j];
                #pragma unroll
                for (int j = 0; j < 4; j++) {
                    acc[0][j] = fmaf(a0, w4[j], acc[0][j]);
                    acc[1][j] = fmaf(a1, w4[j], acc[1][j]);
                }
            }
            __syncthreads();
        }
        #pragma unroll
        for (int i = 0; i < 2; i++) {
            float4 v = make_float4(acc[i][0], acc[i][1], acc[i][2], acc[i][3]);
            *(float4*)&g_T[(m0 + ty * 2 + i) * FC + n0 + tx * 4] = v;
        }
    }
    grid_bar();

    // ============ P5: y_e = w_e * (T[dst] - T[src]) + self-clean ============
    for (int i = gtid; i < E * FC4; i += GT) {
        int e = i >> 6, c4 = i & 63;
        float w = g_w[e];
        int s = ei[e], d = ei[E + e];
        float4 vd = ((const float4*)g_T)[d * FC4 + c4];
        float4 vs = ((const float4*)g_T)[s * FC4 + c4];
        float4 o;
        o.x = w * (vd.x - vs.x); o.y = w * (vd.y - vs.y);
        o.z = w * (vd.z - vs.z); o.w = w * (vd.w - vs.w);
        ((float4*)y)[i] = o;
    }
    // reset scratch for the next graph replay (loader zeroed it for run 1)
    if (gtid < NN) {
        g_hs[gtid] = 0; g_hd[gtid] = 0; g_sl[gtid] = 0;
        g_cur_src[gtid] = 0; g_cur_dst[gtid] = 0;
    }
}

// ---------------- launch ---------------------------------------------------
extern "C" void kernel_launch(void* const* d_in, const int* in_sizes, int n_in,
                              void* d_out, int out_size) {
    const float* x     = (const float*)d_in[0];   // [E, 256]
    const float* W     = (const float*)d_in[1];   // [256, 256]
    const int*   ei    = (const int*)d_in[2];     // [2, E]
    const void*  isdir = d_in[3];                 // [E] bool or int32

    int E = in_sizes[2] / 2;
    float* y = (float*)d_out;

    k_all<<<NB, NT>>>(x, W, ei, isdir, y, E);
}